// round 2
// baseline (speedup 1.0000x reference)
#include <cuda_runtime.h>
#include <cstdint>

#define N_GRAPHS 4096

__device__ float g_sums[N_GRAPHS];
__device__ float g_counts[N_GRAPHS];
__device__ int   g_is64;   // 1 if batch buffer is int64, 0 if int32

__global__ void zero_kernel() {
    int i = blockIdx.x * blockDim.x + threadIdx.x;
    if (i < N_GRAPHS) {
        g_sums[i] = 0.0f;
        g_counts[i] = 0.0f;
    }
}

// Detect whether `batch` is stored as int64 or int32.
// If int64 (little-endian, values < 4096): the int32 view is [v0,0,v1,0,...].
// Sample a window in the middle of the first n int32 words (safe for both
// widths) and test the alternating-zero pattern with nonzero even slots.
__global__ void detect_kernel(const int* __restrict__ b32, int n) {
    int base = (n / 2) & ~1;         // even index, mid-buffer
    if (base + 7 >= n) base = 0;
    bool odd_zero  = (b32[base + 1] == 0) && (b32[base + 3] == 0) &&
                     (b32[base + 5] == 0) && (b32[base + 7] == 0);
    bool even_nz   = (b32[base] != 0) && (b32[base + 2] != 0);
    g_is64 = (odd_zero && even_nz) ? 1 : 0;
}

// Warp-segmented accumulate: batch is sorted, so consecutive nodes share
// segments. Segmented Kogge-Stone suffix reduction per warp; only run-head
// lanes issue global atomics (~1.1 atomics per warp on average).
__global__ void accum_kernel(const float* __restrict__ x,
                             const void* __restrict__ batch,
                             int n, int dfeat) {
    int i = blockIdx.x * blockDim.x + threadIdx.x;
    int lane = threadIdx.x & 31;
    int is64 = g_is64;

    float v = 0.0f;
    float c = 0.0f;
    int seg = -1;
    if (i < n) {
        v = __ldg(&x[(size_t)i * (size_t)dfeat]);
        if (is64) {
            seg = (int)__ldg(&((const long long*)batch)[i]);
        } else {
            seg = __ldg(&((const int*)batch)[i]);
        }
        c = 1.0f;
    }

    const unsigned mask = 0xffffffffu;
    #pragma unroll
    for (int d = 1; d < 32; d <<= 1) {
        float v2 = __shfl_down_sync(mask, v, d);
        float c2 = __shfl_down_sync(mask, c, d);
        int   s2 = __shfl_down_sync(mask, seg, d);
        if (lane + d < 32 && s2 == seg) {
            v += v2;
            c += c2;
        }
    }

    int seg_up = __shfl_up_sync(mask, seg, 1);
    bool head = (lane == 0) || (seg_up != seg);
    if (i < n && head && seg >= 0 && seg < N_GRAPHS) {
        atomicAdd(&g_sums[seg], v);
        atomicAdd(&g_counts[seg], c);
    }
}

__global__ void finalize_kernel(float* __restrict__ out) {
    int i = blockIdx.x * blockDim.x + threadIdx.x;
    if (i < N_GRAPHS) {
        float cnt = g_counts[i];
        out[i] = (cnt > 0.0f) ? (g_sums[i] / cnt) : 0.0f;
    }
}

extern "C" void kernel_launch(void* const* d_in, const int* in_sizes, int n_in,
                              void* d_out, int out_size) {
    // Identify inputs by element count: x is the largest, batch the smallest.
    int xi = 0, bi = 0;
    for (int k = 1; k < n_in; k++) {
        if (in_sizes[k] > in_sizes[xi]) xi = k;
        if (in_sizes[k] < in_sizes[bi]) bi = k;
    }
    const float* x     = (const float*)d_in[xi];
    const void*  batch = d_in[bi];
    float* out = (float*)d_out;

    int n = in_sizes[bi];                 // number of nodes
    int dfeat = in_sizes[xi] / n;         // row stride of x

    detect_kernel<<<1, 1>>>((const int*)batch, n);
    zero_kernel<<<(N_GRAPHS + 255) / 256, 256>>>();

    int threads = 256;
    int blocks = (n + threads - 1) / threads;
    accum_kernel<<<blocks, threads>>>(x, batch, n, dfeat);

    finalize_kernel<<<(N_GRAPHS + 255) / 256, 256>>>(out);
}